// round 17
// baseline (speedup 1.0000x reference)
#include <cuda_runtime.h>
#include <cuda_fp16.h>
#include <cuda_bf16.h>

#define MAXN 100000
#define MAXE 3200000
#define CHUNK 2048
#define MAXNB ((MAXN + CHUNK - 1) / CHUNK)

// Scratch (device globals; allocation is forbidden)
__device__ __half g_hsc[MAXN * 128];   // fp16(hidden * rsqrt(outdeg))
__device__ __half g_aggh[MAXN * 128];  // fp16(rsin * sum hsc[src])
__device__ __half g_H23h[MAXN * 256];  // fp16(hidden @ W_h[:,128:384]) -> [h2 | h3]
__device__ __half g_WhT[256 * 128];    // fp16(W_h[:,128:384])^T : [c][k]
__device__ __half g_WcT[256 * 128];    // fp16(Wc)^T phys-interleaved : [2c+q][k]
__device__ int    g_outdeg[MAXN];
__device__ int    g_indeg[MAXN];
__device__ int    g_rowptr[MAXN + 1];
__device__ int    g_cursor[MAXN];
__device__ int    g_csr[MAXE];
__device__ int    g_flag[MAXNB];       // lookback: 0 = not ready, total+1 otherwise

typedef unsigned int uint;

__device__ __forceinline__ void mma16816(float4& c, uint a0, uint a1, uint a2, uint a3,
                                         uint b0, uint b1) {
    asm volatile(
        "mma.sync.aligned.m16n8k16.row.col.f32.f16.f16.f32 "
        "{%0,%1,%2,%3}, {%4,%5,%6,%7}, {%8,%9}, {%0,%1,%2,%3};"
        : "+f"(c.x), "+f"(c.y), "+f"(c.z), "+f"(c.w)
        : "r"(a0), "r"(a1), "r"(a2), "r"(a3), "r"(b0), "r"(b1));
}

// ---------------------------------------------------------------------------
// Combined weight prep: WhT[c][k] = fp16(W_h[k][128+c]) and
// WcT[phys][k] = fp16( (W_h[:,0:128] @ W_hf)[k][j] ), phys interleaves f1/f2.
__global__ __launch_bounds__(256) void wprep_kernel(const float* __restrict__ W_h,
                                                    const float* __restrict__ W_hf) {
    __shared__ float row[128];
    int k = blockIdx.x;   // 0..127
    int j = threadIdx.x;  // 0..255

    g_WhT[(size_t)j * 128 + k] = __float2half(W_h[(size_t)k * 384 + 128 + j]);

    if (j < 128) row[j] = W_h[(size_t)k * 384 + j];
    __syncthreads();
    float acc = 0.f;
#pragma unroll 8
    for (int m = 0; m < 128; m++) acc = fmaf(row[m], W_hf[(size_t)m * 256 + j], acc);
    int phys = (j < 128) ? (2 * j) : (2 * (j - 128) + 1);
    g_WcT[(size_t)phys * 128 + k] = __float2half(acc);
}

__global__ void outdeg_kernel(const int* __restrict__ src, int e) {
    int i = blockIdx.x * blockDim.x + threadIdx.x;
    int i4 = i * 4;
    if (i4 + 3 < e) {
        int4 s = *reinterpret_cast<const int4*>(&src[i4]);
        atomicAdd(&g_outdeg[s.x], 1); atomicAdd(&g_outdeg[s.y], 1);
        atomicAdd(&g_outdeg[s.z], 1); atomicAdd(&g_outdeg[s.w], 1);
    } else {
        for (int j = i4; j < e; j++) atomicAdd(&g_outdeg[src[j]], 1);
    }
}

__global__ void indeg_kernel(const int* __restrict__ dst, int e) {
    int i = blockIdx.x * blockDim.x + threadIdx.x;
    int i4 = i * 4;
    if (i4 + 3 < e) {
        int4 d = *reinterpret_cast<const int4*>(&dst[i4]);
        atomicAdd(&g_indeg[d.x], 1); atomicAdd(&g_indeg[d.y], 1);
        atomicAdd(&g_indeg[d.z], 1); atomicAdd(&g_indeg[d.w], 1);
    } else {
        for (int j = i4; j < e; j++) atomicAdd(&g_indeg[dst[j]], 1);
    }
}

// ----------------- one-pass decoupled-lookback scan ------------------------
// 49 blocks, all co-resident on 148 SMs -> spin-wait is deadlock-free.
__global__ __launch_bounds__(256) void scan_onepass_kernel(int n, int nb) {
    __shared__ int wsum[8];
    __shared__ int boff_s;
    __shared__ int chunk_total;
    int b = blockIdx.x;
    int base = b * CHUNK;
    int tid = threadIdx.x, lane = tid & 31, wid = tid >> 5;

    int vals[8];
    int s = 0;
#pragma unroll
    for (int j = 0; j < 8; j++) {
        int idx = base + tid * 8 + j;
        vals[j] = (idx < n) ? g_indeg[idx] : 0;
        s += vals[j];
    }
    int x = s;
#pragma unroll
    for (int o = 1; o < 32; o <<= 1) {
        int y = __shfl_up_sync(0xFFFFFFFFu, x, o);
        if (lane >= o) x += y;
    }
    if (lane == 31) wsum[wid] = x;
    __syncthreads();
    if (tid == 0) {
        int acc = 0;
#pragma unroll
        for (int w = 0; w < 8; w++) { int v = wsum[w]; wsum[w] = acc; acc += v; }
        chunk_total = acc;
        // publish this chunk's total (value+1; 0 means "not ready")
        atomicExch(&g_flag[b], acc + 1);
    }
    __syncthreads();

    // lookback: warp 0 sums predecessors' totals
    if (tid < 32) {
        int sum = 0;
        for (int t = lane; t < b; t += 32) {
            int v;
            do { v = atomicAdd(&g_flag[t], 0); } while (v == 0);
            sum += v - 1;
        }
#pragma unroll
        for (int o = 16; o > 0; o >>= 1) sum += __shfl_down_sync(0xFFFFFFFFu, sum, o);
        if (lane == 0) boff_s = sum;
    }
    __syncthreads();

    int boff = boff_s;
    int prefix = boff + wsum[wid] + (x - s);
#pragma unroll
    for (int j = 0; j < 8; j++) {
        int idx = base + tid * 8 + j;
        if (idx < n) { g_rowptr[idx] = prefix; g_cursor[idx] = prefix; }
        prefix += vals[j];
    }
    if (tid == 0 && b == nb - 1) g_rowptr[n] = boff + chunk_total;
}

__global__ void fill_kernel(const int* __restrict__ src, const int* __restrict__ dst, int e) {
    int i = blockIdx.x * blockDim.x + threadIdx.x;
    int i4 = i * 4;
    if (i4 + 3 < e) {
        int4 s = *reinterpret_cast<const int4*>(&src[i4]);
        int4 d = *reinterpret_cast<const int4*>(&dst[i4]);
        g_csr[atomicAdd(&g_cursor[d.x], 1)] = s.x;
        g_csr[atomicAdd(&g_cursor[d.y], 1)] = s.y;
        g_csr[atomicAdd(&g_cursor[d.z], 1)] = s.z;
        g_csr[atomicAdd(&g_cursor[d.w], 1)] = s.w;
    } else {
        for (int j = i4; j < e; j++)
            g_csr[atomicAdd(&g_cursor[dst[j]], 1)] = src[j];
    }
}

// ---------------------------------------------------------------------------
// Gather: one warp per dst node, half-warp per edge, 16B uint4 loads.
__global__ __launch_bounds__(256) void gather_kernel(int n) {
    int node = (blockIdx.x * blockDim.x + threadIdx.x) >> 5;
    int lane = threadIdx.x & 31;
    if (node >= n) return;
    int half = lane >> 4;
    int hl = lane & 15;
    int beg = g_rowptr[node];
    int end = g_rowptr[node + 1];

    float a0 = 0.f, a1 = 0.f, a2 = 0.f, a3 = 0.f;
    float a4 = 0.f, a5 = 0.f, a6 = 0.f, a7 = 0.f;

    int e = beg + half;
    for (; e + 2 < end; e += 4) {
        int s0 = g_csr[e];
        int s1 = g_csr[e + 2];
        uint4 v0 = *reinterpret_cast<const uint4*>(&g_hsc[(size_t)s0 * 128 + hl * 8]);
        uint4 v1 = *reinterpret_cast<const uint4*>(&g_hsc[(size_t)s1 * 128 + hl * 8]);
        float2 p0 = __half22float2(*reinterpret_cast<__half2*>(&v0.x));
        float2 p1 = __half22float2(*reinterpret_cast<__half2*>(&v0.y));
        float2 p2 = __half22float2(*reinterpret_cast<__half2*>(&v0.z));
        float2 p3 = __half22float2(*reinterpret_cast<__half2*>(&v0.w));
        float2 q0 = __half22float2(*reinterpret_cast<__half2*>(&v1.x));
        float2 q1 = __half22float2(*reinterpret_cast<__half2*>(&v1.y));
        float2 q2 = __half22float2(*reinterpret_cast<__half2*>(&v1.z));
        float2 q3 = __half22float2(*reinterpret_cast<__half2*>(&v1.w));
        a0 += p0.x + q0.x; a1 += p0.y + q0.y;
        a2 += p1.x + q1.x; a3 += p1.y + q1.y;
        a4 += p2.x + q2.x; a5 += p2.y + q2.y;
        a6 += p3.x + q3.x; a7 += p3.y + q3.y;
    }
    if (e < end) {
        int s0 = g_csr[e];
        uint4 v0 = *reinterpret_cast<const uint4*>(&g_hsc[(size_t)s0 * 128 + hl * 8]);
        float2 p0 = __half22float2(*reinterpret_cast<__half2*>(&v0.x));
        float2 p1 = __half22float2(*reinterpret_cast<__half2*>(&v0.y));
        float2 p2 = __half22float2(*reinterpret_cast<__half2*>(&v0.z));
        float2 p3 = __half22float2(*reinterpret_cast<__half2*>(&v0.w));
        a0 += p0.x; a1 += p0.y; a2 += p1.x; a3 += p1.y;
        a4 += p2.x; a5 += p2.y; a6 += p3.x; a7 += p3.y;
    }

    a0 += __shfl_down_sync(0xFFFFFFFFu, a0, 16);
    a1 += __shfl_down_sync(0xFFFFFFFFu, a1, 16);
    a2 += __shfl_down_sync(0xFFFFFFFFu, a2, 16);
    a3 += __shfl_down_sync(0xFFFFFFFFu, a3, 16);
    a4 += __shfl_down_sync(0xFFFFFFFFu, a4, 16);
    a5 += __shfl_down_sync(0xFFFFFFFFu, a5, 16);
    a6 += __shfl_down_sync(0xFFFFFFFFu, a6, 16);
    a7 += __shfl_down_sync(0xFFFFFFFFu, a7, 16);

    if (half == 0) {
        float ri = rsqrtf((float)max(end - beg, 1));
        __half2 h0 = __floats2half2_rn(a0 * ri, a1 * ri);
        __half2 h1 = __floats2half2_rn(a2 * ri, a3 * ri);
        __half2 h2 = __floats2half2_rn(a4 * ri, a5 * ri);
        __half2 h3 = __floats2half2_rn(a6 * ri, a7 * ri);
        uint4 st;
        st.x = *reinterpret_cast<uint*>(&h0);
        st.y = *reinterpret_cast<uint*>(&h1);
        st.z = *reinterpret_cast<uint*>(&h2);
        st.w = *reinterpret_cast<uint*>(&h3);
        *reinterpret_cast<uint4*>(&g_aggh[(size_t)node * 128 + hl * 8]) = st;
    }
}

// ---------------------------------------------------------------------------
// GEMM1 (tensor core): H23h[n,256] = fp16( hidden[n,128] @ W_h[:,128:384] )
// BM=128, BN=128, K=128 in smem. col0==0 blocks also emit hsc during A-fill.
__global__ __launch_bounds__(256) void gemm1_mma(const float* __restrict__ hidden, int n) {
    extern __shared__ char smem[];
    __half (*As)[136] = reinterpret_cast<__half(*)[136]>(smem);
    __half (*Bs)[136] = reinterpret_cast<__half(*)[136]>(smem + 34816);
    __half (*Os)[136] = reinterpret_cast<__half(*)[136]>(smem);  // reuse As post-mma

    int tid = threadIdx.x;
    int row0 = blockIdx.y * 128;
    int col0 = blockIdx.x * 128;

#pragma unroll
    for (int i = 0; i < 8; i++) {
        int lin = tid + i * 256;
        int r = lin >> 4;
        int kc = (lin & 15) * 8;
        int grow = row0 + r;
        float4 a = make_float4(0.f, 0.f, 0.f, 0.f), b = a;
        if (grow < n) {
            const float4* p = reinterpret_cast<const float4*>(&hidden[(size_t)grow * 128 + kc]);
            a = p[0]; b = p[1];
        }
        __half2 h0 = __floats2half2_rn(a.x, a.y);
        __half2 h1 = __floats2half2_rn(a.z, a.w);
        __half2 h2 = __floats2half2_rn(b.x, b.y);
        __half2 h3 = __floats2half2_rn(b.z, b.w);
        uint4 o;
        o.x = *reinterpret_cast<uint*>(&h0); o.y = *reinterpret_cast<uint*>(&h1);
        o.z = *reinterpret_cast<uint*>(&h2); o.w = *reinterpret_cast<uint*>(&h3);
        *reinterpret_cast<uint4*>(&As[r][kc]) = o;

        if (col0 == 0 && grow < n) {
            float rs = rsqrtf((float)max(g_outdeg[grow], 1));
            __half2 s0 = __floats2half2_rn(a.x * rs, a.y * rs);
            __half2 s1 = __floats2half2_rn(a.z * rs, a.w * rs);
            __half2 s2 = __floats2half2_rn(b.x * rs, b.y * rs);
            __half2 s3 = __floats2half2_rn(b.z * rs, b.w * rs);
            uint4 os;
            os.x = *reinterpret_cast<uint*>(&s0); os.y = *reinterpret_cast<uint*>(&s1);
            os.z = *reinterpret_cast<uint*>(&s2); os.w = *reinterpret_cast<uint*>(&s3);
            *reinterpret_cast<uint4*>(&g_hsc[(size_t)grow * 128 + kc]) = os;
        }
    }
#pragma unroll
    for (int i = 0; i < 8; i++) {
        int lin = tid + i * 256;
        int r = lin >> 4;
        int kc = (lin & 15) * 8;
        *reinterpret_cast<uint4*>(&Bs[r][kc]) =
            *reinterpret_cast<const uint4*>(&g_WhT[(size_t)(col0 + r) * 128 + kc]);
    }
    __syncthreads();

    int w = tid >> 5, lane = tid & 31;
    int g = lane >> 2, tig = lane & 3;
    int m0 = (w >> 1) * 32;
    int n0 = (w & 1) * 64;

    float4 acc[2][8];
#pragma unroll
    for (int mt = 0; mt < 2; mt++)
#pragma unroll
        for (int j = 0; j < 8; j++) acc[mt][j] = make_float4(0.f, 0.f, 0.f, 0.f);

#pragma unroll
    for (int kt = 0; kt < 128; kt += 16) {
        uint a[2][4];
#pragma unroll
        for (int mt = 0; mt < 2; mt++) {
            int mr = m0 + mt * 16 + g;
            a[mt][0] = *reinterpret_cast<const uint*>(&As[mr][kt + tig * 2]);
            a[mt][1] = *reinterpret_cast<const uint*>(&As[mr + 8][kt + tig * 2]);
            a[mt][2] = *reinterpret_cast<const uint*>(&As[mr][kt + tig * 2 + 8]);
            a[mt][3] = *reinterpret_cast<const uint*>(&As[mr + 8][kt + tig * 2 + 8]);
        }
#pragma unroll
        for (int j = 0; j < 8; j++) {
            int nc = n0 + j * 8 + g;
            uint b0 = *reinterpret_cast<const uint*>(&Bs[nc][kt + tig * 2]);
            uint b1 = *reinterpret_cast<const uint*>(&Bs[nc][kt + tig * 2 + 8]);
            mma16816(acc[0][j], a[0][0], a[0][1], a[0][2], a[0][3], b0, b1);
            mma16816(acc[1][j], a[1][0], a[1][1], a[1][2], a[1][3], b0, b1);
        }
    }
    __syncthreads();

#pragma unroll
    for (int mt = 0; mt < 2; mt++) {
#pragma unroll
        for (int j = 0; j < 8; j++) {
            int r1 = m0 + mt * 16 + g;
            int c = n0 + j * 8 + tig * 2;
            __half2 lo = __floats2half2_rn(acc[mt][j].x, acc[mt][j].y);
            __half2 hi = __floats2half2_rn(acc[mt][j].z, acc[mt][j].w);
            *reinterpret_cast<uint*>(&Os[r1][c]) = *reinterpret_cast<uint*>(&lo);
            *reinterpret_cast<uint*>(&Os[r1 + 8][c]) = *reinterpret_cast<uint*>(&hi);
        }
    }
    __syncthreads();
#pragma unroll
    for (int i = 0; i < 8; i++) {
        int lin = tid + i * 256;
        int r = lin >> 4;
        int kc = (lin & 15) * 8;
        if (row0 + r < n)
            *reinterpret_cast<uint4*>(&g_H23h[(size_t)(row0 + r) * 256 + col0 + kc]) =
                *reinterpret_cast<const uint4*>(&Os[r][kc]);
    }
}

// ---------------------------------------------------------------------------
// GEMM2 (tensor core) fused with gated epilogue; smem-staged I/O.
__global__ __launch_bounds__(256) void gemm2_mma(float* __restrict__ out, int n, int dup) {
    extern __shared__ char smem[];
    __half (*As)[136] = reinterpret_cast<__half(*)[136]>(smem);
    __half (*Bs)[136] = reinterpret_cast<__half(*)[136]>(smem + 34816);
    __half (*H2s)[72] = reinterpret_cast<__half(*)[72]>(smem + 34816);            // reuse Bs
    __half (*H3s)[72] = reinterpret_cast<__half(*)[72]>(smem + 34816 + 18432);
    float (*Os)[68]   = reinterpret_cast<float(*)[68]>(smem);                     // reuse As

    int tid = threadIdx.x;
    int row0 = blockIdx.y * 128;
    int col0 = blockIdx.x * 128;
    int q0 = col0 >> 1;

#pragma unroll
    for (int i = 0; i < 8; i++) {
        int lin = tid + i * 256;
        int r = lin >> 4;
        int kc = (lin & 15) * 8;
        uint4 v = make_uint4(0, 0, 0, 0);
        if (row0 + r < n)
            v = *reinterpret_cast<const uint4*>(&g_aggh[(size_t)(row0 + r) * 128 + kc]);
        *reinterpret_cast<uint4*>(&As[r][kc]) = v;
    }
#pragma unroll
    for (int i = 0; i < 8; i++) {
        int lin = tid + i * 256;
        int r = lin >> 4;
        int kc = (lin & 15) * 8;
        *reinterpret_cast<uint4*>(&Bs[r][kc]) =
            *reinterpret_cast<const uint4*>(&g_WcT[(size_t)(col0 + r) * 128 + kc]);
    }
    __syncthreads();

    int w = tid >> 5, lane = tid & 31;
    int g = lane >> 2, tig = lane & 3;
    int m0 = (w >> 1) * 32;
    int n0 = (w & 1) * 64;

    float4 acc[2][8];
#pragma unroll
    for (int mt = 0; mt < 2; mt++)
#pragma unroll
        for (int j = 0; j < 8; j++) acc[mt][j] = make_float4(0.f, 0.f, 0.f, 0.f);

#pragma unroll
    for (int kt = 0; kt < 128; kt += 16) {
        uint a[2][4];
#pragma unroll
        for (int mt = 0; mt < 2; mt++) {
            int mr = m0 + mt * 16 + g;
            a[mt][0] = *reinterpret_cast<const uint*>(&As[mr][kt + tig * 2]);
            a[mt][1] = *reinterpret_cast<const uint*>(&As[mr + 8][kt + tig * 2]);
            a[mt][2] = *reinterpret_cast<const uint*>(&As[mr][kt + tig * 2 + 8]);
            a[mt][3] = *reinterpret_cast<const uint*>(&As[mr + 8][kt + tig * 2 + 8]);
        }
#pragma unroll
        for (int j = 0; j < 8; j++) {
            int nc = n0 + j * 8 + g;
            uint b0 = *reinterpret_cast<const uint*>(&Bs[nc][kt + tig * 2]);
            uint b1 = *reinterpret_cast<const uint*>(&Bs[nc][kt + tig * 2 + 8]);
            mma16816(acc[0][j], a[0][0], a[0][1], a[0][2], a[0][3], b0, b1);
            mma16816(acc[1][j], a[1][0], a[1][1], a[1][2], a[1][3], b0, b1);
        }
    }
    __syncthreads();

#pragma unroll
    for (int i = 0; i < 8; i++) {
        int lin = tid + i * 256;
        int a = lin >> 10;
        int rem = lin & 1023;
        int r = rem >> 3;
        int c8 = (rem & 7) * 8;
        uint4 v = make_uint4(0, 0, 0, 0);
        if (row0 + r < n)
            v = *reinterpret_cast<const uint4*>(
                &g_H23h[(size_t)(row0 + r) * 256 + a * 128 + q0 + c8]);
        if (a == 0) *reinterpret_cast<uint4*>(&H2s[r][c8]) = v;
        else        *reinterpret_cast<uint4*>(&H3s[r][c8]) = v;
    }
    __syncthreads();

#pragma unroll
    for (int mt = 0; mt < 2; mt++) {
#pragma unroll
        for (int j = 0; j < 8; j++) {
            int r1 = m0 + mt * 16 + g;
            int r2 = r1 + 8;
            int qloc = (n0 >> 1) + j * 4 + tig;
            float h2a = __half2float(H2s[r1][qloc]);
            float h3a = __half2float(H3s[r1][qloc]);
            Os[r1][qloc] = h3a + fmaxf(acc[mt][j].x + h2a, 0.f) * acc[mt][j].y;
            float h2b = __half2float(H2s[r2][qloc]);
            float h3b = __half2float(H3s[r2][qloc]);
            Os[r2][qloc] = h3b + fmaxf(acc[mt][j].z + h2b, 0.f) * acc[mt][j].w;
        }
    }
    __syncthreads();

    size_t ndup = (size_t)n * 128;
#pragma unroll
    for (int i = 0; i < 8; i++) {
        int lin = tid + i * 256;
        int r = lin >> 4;
        int c4 = (lin & 15) * 4;
        if (row0 + r < n) {
            float4 v = *reinterpret_cast<const float4*>(&Os[r][c4]);
            size_t off = (size_t)(row0 + r) * 128 + q0 + c4;
            *reinterpret_cast<float4*>(&out[off]) = v;
            if (dup) *reinterpret_cast<float4*>(&out[ndup + off]) = v;
        }
    }
}

// ---------------------------------------------------------------------------
extern "C" void kernel_launch(void* const* d_in, const int* in_sizes, int n_in,
                              void* d_out, int out_size) {
    const float* hidden = (const float*)d_in[0];
    const int*   src    = (const int*)d_in[1];
    const int*   dst    = (const int*)d_in[2];
    const float* W_h    = (const float*)d_in[3];
    const float* W_hf   = (const float*)d_in[4];
    float* out = (float*)d_out;

    int n = in_sizes[0] / 128;
    int e = in_sizes[1];
    int nb = (n + CHUNK - 1) / CHUNK;
    int dup = (out_size >= 2 * n * 128) ? 1 : 0;
    const int SMEM_G1 = 2 * 34816;                 // 69632
    const int SMEM_G2 = 34816 + 2 * (128 * 144);   // 71680

    // Lazy one-time resources (created on the non-captured correctness call).
    static cudaStream_t side = nullptr;
    static cudaEvent_t ev_fork = nullptr, ev_zero = nullptr, ev_join = nullptr;
    static int* p_outdeg = nullptr;
    static int* p_indeg = nullptr;
    static int* p_flag = nullptr;
    if (side == nullptr) {
        cudaStreamCreateWithFlags(&side, cudaStreamNonBlocking);
        cudaEventCreateWithFlags(&ev_fork, cudaEventDisableTiming);
        cudaEventCreateWithFlags(&ev_zero, cudaEventDisableTiming);
        cudaEventCreateWithFlags(&ev_join, cudaEventDisableTiming);
        cudaGetSymbolAddress((void**)&p_outdeg, g_outdeg);
        cudaGetSymbolAddress((void**)&p_indeg, g_indeg);
        cudaGetSymbolAddress((void**)&p_flag, g_flag);
        cudaFuncSetAttribute(gemm1_mma, cudaFuncAttributeMaxDynamicSharedMemorySize, SMEM_G1);
        cudaFuncSetAttribute(gemm2_mma, cudaFuncAttributeMaxDynamicSharedMemorySize, SMEM_G2);
    }

    // ---- fork ----
    cudaEventRecord(ev_fork, 0);
    cudaStreamWaitEvent(side, ev_fork, 0);
    wprep_kernel<<<128, 256, 0, side>>>(W_h, W_hf);   // WhT (gemm1) + WcT (gemm2)

    // main: zero degree arrays + lookback flags via memset
    cudaMemsetAsync(p_outdeg, 0, (size_t)n * sizeof(int), 0);
    cudaMemsetAsync(p_indeg, 0, (size_t)n * sizeof(int), 0);
    cudaMemsetAsync(p_flag, 0, (size_t)nb * sizeof(int), 0);
    cudaEventRecord(ev_zero, 0);

    // side: outdeg -> gemm1 (emits H23h + hsc)
    cudaStreamWaitEvent(side, ev_zero, 0);
    outdeg_kernel<<<(e / 4 + 255) / 256, 256, 0, side>>>(src, e);
    gemm1_mma<<<dim3(2, (n + 127) / 128), 256, SMEM_G1, side>>>(hidden, n);
    cudaEventRecord(ev_join, side);

    // main: indeg -> one-pass scan -> fill
    indeg_kernel<<<(e / 4 + 255) / 256, 256>>>(dst, e);
    scan_onepass_kernel<<<nb, 256>>>(n, nb);
    fill_kernel<<<(e / 4 + 255) / 256, 256>>>(src, dst, e);

    // ---- join: gather needs hsc (gemm1) + csr; gemm2 needs WcT + H23h ----
    cudaStreamWaitEvent(0, ev_join, 0);
    gather_kernel<<<(n * 32 + 255) / 256, 256>>>(n);
    gemm2_mma<<<dim3(2, (n + 127) / 128), 256, SMEM_G2>>>(out, n, dup);
}